// round 7
// baseline (speedup 1.0000x reference)
#include <cuda_runtime.h>
#include <math.h>

#define Nn 2000
#define Ee 20000
#define Cc 16
#define Bb 128
#define EPS 1e-5f
#define NB 1628          // 148 SMs x 11 blocks/SM, all co-resident (<=46 regs)

__device__ __forceinline__ bool is_func(int n) { return n >= 200 && n < 1800; }

// ---------------- device scratch (allocation-free) --------------------------
__device__ float g_xT[Nn * Bb];
__device__ float g_xeA[Ee * Bb];
__device__ float g_xeB[Ee * Bb];
__device__ float g_pw1[Ee * Cc];       // w1 in dst-CSR order
__device__ float g_pw3m[Ee * Cc];      // w3*fm[src] in src-CSR order
__device__ float g_pb3[Ee];            // b3 in src-CSR order
__device__ int   g_psrcd[Ee];          // src-node row offset (pre-scaled *Bb), dst order
__device__ int   g_rowidx[Ee];         // src-CSR row offset (pre-scaled *Bb), dst order
__device__ int   g_cntD[Nn], g_cntS[Nn];   // zero at load; re-zeroed in final phase
__device__ int   g_rsD[Nn + 1], g_rsS[Nn + 1];
__device__ int   g_curD[Nn], g_curS[Nn];
__device__ unsigned g_bcount, g_bgen;      // grid barrier state (reset in k_build)

// ---------------- preprocessing ---------------------------------------------
__global__ void k_init(const float* __restrict__ x,
                       const int* __restrict__ src, const int* __restrict__ dst) {
    int t = blockIdx.x * blockDim.x + threadIdx.x;
    if (t < Ee) {
        atomicAdd(&g_cntD[dst[t]], 1);
        atomicAdd(&g_cntS[src[t]], 1);
    }
    if (t < Nn * Bb) {
        int n = t >> 7, b = t & 127;
        g_xT[t] = x[b * Nn + n];
    }
}

__global__ void __launch_bounds__(1024) k_scan() {
    __shared__ int sh[2048];
    const int* cnt = blockIdx.x ? g_cntS : g_cntD;
    int* rs  = blockIdx.x ? g_rsS : g_rsD;
    int* cur = blockIdx.x ? g_curS : g_curD;
    int t = threadIdx.x;
    sh[t]        = (t < Nn) ? cnt[t] : 0;
    sh[t + 1024] = (t + 1024 < Nn) ? cnt[t + 1024] : 0;
    __syncthreads();
    for (int off = 1; off < 2048; off <<= 1) {
        int v0 = (t >= off) ? sh[t - off] : 0;
        int v1 = (t + 1024 >= off) ? sh[t + 1024 - off] : 0;
        __syncthreads();
        sh[t] += v0;
        sh[t + 1024] += v1;
        __syncthreads();
    }
    if (t < Nn) {
        int v = (t == 0) ? 0 : sh[t - 1];
        rs[t] = v; cur[t] = v;
    }
    int i2 = t + 1024;
    if (i2 < Nn) {
        int v = sh[i2 - 1];
        rs[i2] = v; cur[i2] = v;
    }
    if (t == 0) rs[Nn] = sh[Nn - 1];
}

__global__ void k_build(const float* __restrict__ w1, const float* __restrict__ w3,
                        const float* __restrict__ b3,
                        const int* __restrict__ src, const int* __restrict__ dst) {
    int e = blockIdx.x * blockDim.x + threadIdx.x;
    if (e == 0) { g_bcount = 0u; g_bgen = 0u; }     // arm grid barrier for k_mega
    if (e >= Ee) return;
    int s = src[e], d = dst[e];
    int pd = atomicAdd(&g_curD[d], 1);
    int ps = atomicAdd(&g_curS[s], 1);
    g_psrcd[pd]  = s * Bb;       // pre-scaled row offsets
    g_rowidx[pd] = ps * Bb;
    g_pb3[ps]    = b3[e];
    float fm = is_func(s) ? 1.0f : 0.0f;
    const float4* w1p = (const float4*)(w1 + e * 16);
    const float4* w3p = (const float4*)(w3 + e * 16);
    float4* o1 = (float4*)(g_pw1 + pd * 16);
    float4* o3 = (float4*)(g_pw3m + ps * 16);
#pragma unroll
    for (int k = 0; k < 4; k++) {
        o1[k] = w1p[k];
        float4 w = w3p[k];
        o3[k] = make_float4(w.x * fm, w.y * fm, w.z * fm, w.w * fm);
    }
}

// ---------------- grid barrier (cumulative counter, no reset race) ----------
__device__ __forceinline__ void gbar(int k) {
    __syncthreads();
    if (threadIdx.x == 0) {
        __threadfence();
        unsigned v = atomicAdd(&g_bcount, 1u);
        if (v == (unsigned)NB * (unsigned)(k + 1) - 1u) {
            atomicExch(&g_bgen, (unsigned)(k + 1));
        } else {
            while (atomicAdd(&g_bgen, 0u) < (unsigned)(k + 1)) __nanosleep(64);
        }
    }
    __syncthreads();
}

// ---------------- shared layout ---------------------------------------------
struct SmemT {
    float4 shw4[16][4];
    float  shh[128][17];
    float  shs[8][16], shs2[8][16];
    float  shscale[16], shshift[16];
};

// ---------------- BN + ELU --------------------------------------------------
__device__ __forceinline__ void bn_elu(float* acc, int n, int b,
                                       const float* __restrict__ gamma,
                                       const float* __restrict__ beta,
                                       SmemT* sm) {
    __syncthreads();
#pragma unroll
    for (int c = 0; c < 16; c++) sm->shh[b][c] = acc[c];
    __syncthreads();
    int c0 = b & 15, gg = b >> 4;
    float s = 0.f, s2 = 0.f;
#pragma unroll
    for (int k = 0; k < 16; k++) {
        float v = sm->shh[gg + 8 * k][c0];
        s += v; s2 += v * v;
    }
    sm->shs[gg][c0] = s;
    sm->shs2[gg][c0] = s2;
    __syncthreads();
    if (b < 16) {
        float S = 0.f, S2 = 0.f;
#pragma unroll
        for (int g = 0; g < 8; g++) { S += sm->shs[g][b]; S2 += sm->shs2[g][b]; }
        float m   = S * (1.0f / 128.0f);
        float var = S2 * (1.0f / 128.0f) - m * m;
        float rsg = rsqrtf(var + EPS);
        float sc  = gamma[n * 16 + b] * rsg;
        sm->shscale[b] = sc;
        sm->shshift[b] = beta[n * 16 + b] - m * sc;
    }
    __syncthreads();
#pragma unroll
    for (int c = 0; c < 16; c++) {
        float v = acc[c] * sm->shscale[c] + sm->shshift[c];
        acc[c] = v > 0.f ? v : (__expf(v) - 1.0f);
    }
}

// ---------------- the persistent mega kernel --------------------------------
// 4 compute phases share ONE inlined node body (register- and icache-friendly),
// then the final output phase.
__global__ void __launch_bounds__(128, 11) k_mega(
    float* __restrict__ outp,
    const float* __restrict__ b1, const float* __restrict__ w2,
    const float* __restrict__ b2,
    const float* __restrict__ g1, const float* __restrict__ be1,
    const float* __restrict__ g2, const float* __restrict__ be2) {
    __shared__ SmemT sm;
    int b = threadIdx.x;

    for (int ph = 0; ph < 4; ph++) {
        const float* xe_rows = (ph == 0) ? g_xT : ((ph & 1) ? g_xeA : g_xeB);
        float*       xe_out  = (ph & 1) ? g_xeB : g_xeA;
        const int*   rowix   = (ph == 0) ? g_psrcd : g_rowidx;
        int ntask = (ph == 0) ? 2000 : 1600;

        for (int t = blockIdx.x; t < ntask; t += NB) {
            if (t < 1600) {
                // ---- one node's full layer step (inlined once) ----
                int n = 200 + t;
                float acc[16];
#pragma unroll
                for (int c = 0; c < 16; c++) acc[c] = b1[n * 16 + c];

                int rs = g_rsD[n], re = g_rsD[n + 1];
                for (int base = rs; base < re; base += 8) {
                    float xv[8];
#pragma unroll
                    for (int j = 0; j < 8; j++) {
                        int p = base + j;
                        xv[j] = (p < re) ? __ldcg(&xe_rows[rowix[p] + b]) : 0.0f;
                    }
#pragma unroll
                    for (int j = 0; j < 8; j++) {
                        int p = base + j;
                        if (p < re) {
                            const float4* wp = (const float4*)(g_pw1 + p * 16);
                            float4 w0 = wp[0], w1v = wp[1], w2v = wp[2], w3v = wp[3];
                            float v = xv[j];
                            acc[0]  += v * w0.x;  acc[1]  += v * w0.y;
                            acc[2]  += v * w0.z;  acc[3]  += v * w0.w;
                            acc[4]  += v * w1v.x; acc[5]  += v * w1v.y;
                            acc[6]  += v * w1v.z; acc[7]  += v * w1v.w;
                            acc[8]  += v * w2v.x; acc[9]  += v * w2v.y;
                            acc[10] += v * w2v.z; acc[11] += v * w2v.w;
                            acc[12] += v * w3v.x; acc[13] += v * w3v.y;
                            acc[14] += v * w3v.z; acc[15] += v * w3v.w;
                        }
                    }
                }

                bn_elu(acc, n, b, g1, be1, &sm);

                __syncthreads();
#pragma unroll
                for (int c = 0; c < 16; c++) sm.shh[b][c] = acc[c];
                {
                    const float4* w2p = (const float4*)(w2 + n * 256);
                    for (int i = b; i < 64; i += 128) sm.shw4[i >> 2][i & 3] = w2p[i];
                }
                __syncthreads();

                float out[16];
#pragma unroll
                for (int d = 0; d < 16; d++) out[d] = b2[n * 16 + d];
#pragma unroll
                for (int c = 0; c < 16; c++) {
                    float v = sm.shh[b][c];
                    float4 r0 = sm.shw4[c][0], r1 = sm.shw4[c][1];
                    float4 r2 = sm.shw4[c][2], r3 = sm.shw4[c][3];
                    out[0]  += v * r0.x;  out[1]  += v * r0.y;
                    out[2]  += v * r0.z;  out[3]  += v * r0.w;
                    out[4]  += v * r1.x;  out[5]  += v * r1.y;
                    out[6]  += v * r1.z;  out[7]  += v * r1.w;
                    out[8]  += v * r2.x;  out[9]  += v * r2.y;
                    out[10] += v * r2.z;  out[11] += v * r2.w;
                    out[12] += v * r3.x;  out[13] += v * r3.y;
                    out[14] += v * r3.z;  out[15] += v * r3.w;
                }

                bn_elu(out, n, b, g2, be2, &sm);

                float xb = g_xT[n * Bb + b];
                int qs = g_rsS[n], qe = g_rsS[n + 1];
#pragma unroll 2
                for (int q = qs; q < qe; q++) {
                    const float4* wq = (const float4*)(g_pw3m + q * 16);
                    float4 w0 = wq[0], w1v = wq[1], w2v = wq[2], w3v = wq[3];
                    float d = out[0]  * w0.x  + out[1]  * w0.y  + out[2]  * w0.z  + out[3]  * w0.w
                            + out[4]  * w1v.x + out[5]  * w1v.y + out[6]  * w1v.z + out[7]  * w1v.w
                            + out[8]  * w2v.x + out[9]  * w2v.y + out[10] * w2v.z + out[11] * w2v.w
                            + out[12] * w3v.x + out[13] * w3v.y + out[14] * w3v.z + out[15] * w3v.w;
                    xe_out[q * Bb + b] = xb + g_pb3[q] + d;
                }
            } else {
                // const edge rows (only in phase 0; tasks 1600..1999)
                int i = t - 1600;
                int n = (i < 200) ? i : (1600 + i);     // [0,200) U [1800,2000)
                float xb = g_xT[n * Bb + b];
                int qs = g_rsS[n], qe = g_rsS[n + 1];
                for (int q = qs; q < qe; q++) {
                    float v = xb + g_pb3[q];
                    g_xeA[q * Bb + b] = v;
                    g_xeB[q * Bb + b] = v;
                }
            }
        }
        gbar(ph);
    }

    // final: segment sum + masked transpose + count re-zero
    for (int n = blockIdx.x; n < Nn; n += NB) {
        float s = 0.f;
        if (n >= 1800) {
            int rs = g_rsD[n], re = g_rsD[n + 1];
            for (int p = rs; p < re; p++) s += __ldcg(&g_xeB[g_rowidx[p] + b]);
        }
        outp[b * Nn + n] = s;
        if (b == 0) { g_cntD[n] = 0; g_cntS[n] = 0; }
    }
}

// ---------------- launch ----------------------------------------------------
extern "C" void kernel_launch(void* const* d_in, const int* in_sizes, int n_in,
                              void* d_out, int out_size) {
    const float* x   = (const float*)d_in[0];
    const float* w1  = (const float*)d_in[1];
    const float* b1  = (const float*)d_in[2];
    const float* w2  = (const float*)d_in[3];
    const float* b2  = (const float*)d_in[4];
    const float* w3  = (const float*)d_in[5];
    const float* b3  = (const float*)d_in[6];
    const float* g1  = (const float*)d_in[7];
    const float* be1 = (const float*)d_in[8];
    const float* g2  = (const float*)d_in[9];
    const float* be2 = (const float*)d_in[10];
    const int*   ei  = (const int*)d_in[11];
    float* out = (float*)d_out;

    const int* src = ei;
    const int* dst = ei + Ee;

    k_init<<<(Nn * Bb + 255) / 256, 256>>>(x, src, dst);
    k_scan<<<2, 1024>>>();
    k_build<<<(Ee + 255) / 256, 256>>>(w1, w3, b3, src, dst);
    k_mega<<<NB, 128>>>(out, b1, w2, b2, g1, be1, g2, be2);
}

// round 8
// speedup vs baseline: 1.6083x; 1.6083x over previous
#include <cuda_runtime.h>
#include <math.h>

#define Nn 2000
#define Ee 20000
#define Cc 16
#define Bb 128
#define EPS 1e-5f
#define CHUNK 128   // edges staged per smem chunk

__device__ __forceinline__ bool is_func(int n) { return n >= 200 && n < 1800; }

// ---------------- device scratch (allocation-free) --------------------------
__device__ float g_xT[Nn * Bb];
__device__ float g_xeA[Ee * Bb];
__device__ float g_xeB[Ee * Bb];
__device__ float g_pw1[Ee * Cc];       // w1 in dst-CSR order
__device__ float g_pw3m[Ee * Cc];      // w3*fm[src] in src-CSR order
__device__ float g_pb3[Ee];            // b3 in src-CSR order
__device__ int   g_psrcd[Ee];          // src-node row offset (*Bb), dst order
__device__ int   g_rowidx[Ee];         // src-CSR row offset (*Bb), dst order
__device__ int   g_cntD[Nn], g_cntS[Nn];   // zero at load; re-zeroed by k_final
__device__ int   g_rsD[Nn + 1], g_rsS[Nn + 1];
__device__ int   g_curD[Nn], g_curS[Nn];

// ---------------- preprocessing ---------------------------------------------
__global__ void k_init(const float* __restrict__ x,
                       const int* __restrict__ src, const int* __restrict__ dst) {
    int t = blockIdx.x * blockDim.x + threadIdx.x;
    if (t < Ee) {
        atomicAdd(&g_cntD[dst[t]], 1);
        atomicAdd(&g_cntS[src[t]], 1);
    }
    if (t < Nn * Bb) {
        int n = t >> 7, b = t & 127;
        g_xT[t] = x[b * Nn + n];
    }
}

__global__ void __launch_bounds__(1024) k_scan() {
    __shared__ int sh[2048];
    const int* cnt = blockIdx.x ? g_cntS : g_cntD;
    int* rs  = blockIdx.x ? g_rsS : g_rsD;
    int* cur = blockIdx.x ? g_curS : g_curD;
    int t = threadIdx.x;
    sh[t]        = (t < Nn) ? cnt[t] : 0;
    sh[t + 1024] = (t + 1024 < Nn) ? cnt[t + 1024] : 0;
    __syncthreads();
    for (int off = 1; off < 2048; off <<= 1) {
        int v0 = (t >= off) ? sh[t - off] : 0;
        int v1 = (t + 1024 >= off) ? sh[t + 1024 - off] : 0;
        __syncthreads();
        sh[t] += v0;
        sh[t + 1024] += v1;
        __syncthreads();
    }
    if (t < Nn) {
        int v = (t == 0) ? 0 : sh[t - 1];
        rs[t] = v; cur[t] = v;
    }
    int i2 = t + 1024;
    if (i2 < Nn) {
        int v = sh[i2 - 1];
        rs[i2] = v; cur[i2] = v;
    }
    if (t == 0) rs[Nn] = sh[Nn - 1];
}

__global__ void k_build(const float* __restrict__ w1, const float* __restrict__ w3,
                        const float* __restrict__ b3,
                        const int* __restrict__ src, const int* __restrict__ dst) {
    int e = blockIdx.x * blockDim.x + threadIdx.x;
    if (e >= Ee) return;
    int s = src[e], d = dst[e];
    int pd = atomicAdd(&g_curD[d], 1);
    int ps = atomicAdd(&g_curS[s], 1);
    g_psrcd[pd]  = s * Bb;
    g_rowidx[pd] = ps * Bb;
    g_pb3[ps]    = b3[e];
    float fm = is_func(s) ? 1.0f : 0.0f;
    const float4* w1p = (const float4*)(w1 + e * 16);
    const float4* w3p = (const float4*)(w3 + e * 16);
    float4* o1 = (float4*)(g_pw1 + pd * 16);
    float4* o3 = (float4*)(g_pw3m + ps * 16);
#pragma unroll
    for (int k = 0; k < 4; k++) {
        o1[k] = w1p[k];
        float4 w = w3p[k];
        o3[k] = make_float4(w.x * fm, w.y * fm, w.z * fm, w.w * fm);
    }
}

// ---------------- shared layout (stage aliases shh; usage disjoint) ----------
struct SmemT {
    union {
        float stage[CHUNK * 16];   // 8192B  edge-weight staging
        float shh[128][17];        // 8704B  BN scratch / h parking
    };
    float4 shw4[16][4];
    float  shs[8][16], shs2[8][16];
    float  shscale[16], shshift[16];
    int    sidx[CHUNK];            // staged rowidx
    float  sb3[CHUNK];             // staged b3
};

// ---------------- BN + ELU --------------------------------------------------
__device__ __forceinline__ void bn_elu(float* acc, int n, int b,
                                       const float* __restrict__ gamma,
                                       const float* __restrict__ beta,
                                       SmemT* sm) {
    __syncthreads();
#pragma unroll
    for (int c = 0; c < 16; c++) sm->shh[b][c] = acc[c];
    __syncthreads();
    int c0 = b & 15, gg = b >> 4;
    float s = 0.f, s2 = 0.f;
#pragma unroll
    for (int k = 0; k < 16; k++) {
        float v = sm->shh[gg + 8 * k][c0];
        s += v; s2 += v * v;
    }
    sm->shs[gg][c0] = s;
    sm->shs2[gg][c0] = s2;
    __syncthreads();
    if (b < 16) {
        float S = 0.f, S2 = 0.f;
#pragma unroll
        for (int g = 0; g < 8; g++) { S += sm->shs[g][b]; S2 += sm->shs2[g][b]; }
        float m   = S * (1.0f / 128.0f);
        float var = S2 * (1.0f / 128.0f) - m * m;
        float rsg = rsqrtf(var + EPS);
        float sc  = gamma[n * 16 + b] * rsg;
        sm->shscale[b] = sc;
        sm->shshift[b] = beta[n * 16 + b] - m * sc;
    }
    __syncthreads();
#pragma unroll
    for (int c = 0; c < 16; c++) {
        float v = acc[c] * sm->shscale[c] + sm->shshift[c];
        acc[c] = v > 0.f ? v : (__expf(v) - 1.0f);
    }
}

// ---------------- fused per-layer kernel -------------------------------------
// grid = 1600 (func nodes); layer 0 uses grid = 2000, where blocks >= 1600
// write the layer-invariant const edge rows into both ping-pong buffers.
__global__ void __launch_bounds__(128, 11) k_layer(
    const float* __restrict__ xe_rows, int use_psrc,
    float* __restrict__ xe_out,
    const float* __restrict__ b1, const float* __restrict__ w2,
    const float* __restrict__ b2,
    const float* __restrict__ g1, const float* __restrict__ be1,
    const float* __restrict__ g2, const float* __restrict__ be2) {
    __shared__ SmemT sm;
    int t = blockIdx.x;
    int b = threadIdx.x;

    if (t >= 1600) {   // const-edge writer (layer-0 grid only)
        int i = t - 1600;
        int n = (i < 200) ? i : (1600 + i);     // [0,200) U [1800,2000)
        float xb = g_xT[n * Bb + b];
        int qs = g_rsS[n], qe = g_rsS[n + 1];
        for (int q = qs; q < qe; q++) {
            float v = xb + g_pb3[q];
            g_xeA[q * Bb + b] = v;
            g_xeB[q * Bb + b] = v;
        }
        return;
    }

    int n = 200 + t;
    const int* rowix = use_psrc ? g_psrcd : g_rowidx;

    float acc[16];
#pragma unroll
    for (int c = 0; c < 16; c++) acc[c] = b1[n * 16 + c];

    // ---- gather in-edges: smem-staged weights+indices, 8-wide xv prefetch ----
    int rs = g_rsD[n], re = g_rsD[n + 1];
    for (int cbase = rs; cbase < re; cbase += CHUNK) {
        int cnt = min(CHUNK, re - cbase);
        __syncthreads();
        for (int i = b; i < cnt * 16; i += 128) sm.stage[i] = g_pw1[cbase * 16 + i];
        if (b < cnt) sm.sidx[b] = rowix[cbase + b];
        __syncthreads();
        for (int jb = 0; jb < cnt; jb += 8) {
            float xv[8];
#pragma unroll
            for (int j = 0; j < 8; j++) {
                int jj = jb + j;
                xv[j] = (jj < cnt) ? xe_rows[sm.sidx[jj] + b] : 0.0f;
            }
#pragma unroll
            for (int j = 0; j < 8; j++) {
                int jj = jb + j;
                if (jj < cnt) {
                    const float4* wp = (const float4*)&sm.stage[jj * 16];
                    float4 w0 = wp[0], w1v = wp[1], w2v = wp[2], w3v = wp[3];
                    float v = xv[j];
                    acc[0]  += v * w0.x;  acc[1]  += v * w0.y;
                    acc[2]  += v * w0.z;  acc[3]  += v * w0.w;
                    acc[4]  += v * w1v.x; acc[5]  += v * w1v.y;
                    acc[6]  += v * w1v.z; acc[7]  += v * w1v.w;
                    acc[8]  += v * w2v.x; acc[9]  += v * w2v.y;
                    acc[10] += v * w2v.z; acc[11] += v * w2v.w;
                    acc[12] += v * w3v.x; acc[13] += v * w3v.y;
                    acc[14] += v * w3v.z; acc[15] += v * w3v.w;
                }
            }
        }
    }

    bn_elu(acc, n, b, g1, be1, &sm);

    // ---- 16x16 matmul: park h in shh, weights in shw4 ----
    __syncthreads();
#pragma unroll
    for (int c = 0; c < 16; c++) sm.shh[b][c] = acc[c];
    {
        const float4* w2p = (const float4*)(w2 + n * 256);
        for (int i = b; i < 64; i += 128) sm.shw4[i >> 2][i & 3] = w2p[i];
    }
    __syncthreads();

    float out[16];
#pragma unroll
    for (int d = 0; d < 16; d++) out[d] = b2[n * 16 + d];
#pragma unroll
    for (int c = 0; c < 16; c++) {
        float v = sm.shh[b][c];
        float4 r0 = sm.shw4[c][0], r1 = sm.shw4[c][1];
        float4 r2 = sm.shw4[c][2], r3 = sm.shw4[c][3];
        out[0]  += v * r0.x;  out[1]  += v * r0.y;
        out[2]  += v * r0.z;  out[3]  += v * r0.w;
        out[4]  += v * r1.x;  out[5]  += v * r1.y;
        out[6]  += v * r1.z;  out[7]  += v * r1.w;
        out[8]  += v * r2.x;  out[9]  += v * r2.y;
        out[10] += v * r2.z;  out[11] += v * r2.w;
        out[12] += v * r3.x;  out[13] += v * r3.y;
        out[14] += v * r3.z;  out[15] += v * r3.w;
    }

    bn_elu(out, n, b, g2, be2, &sm);

    // ---- scatter out-edges: smem-staged w3m + b3 ----
    float xb = g_xT[n * Bb + b];
    int qs = g_rsS[n], qe = g_rsS[n + 1];
    for (int cbase = qs; cbase < qe; cbase += CHUNK) {
        int cnt = min(CHUNK, qe - cbase);
        __syncthreads();
        for (int i = b; i < cnt * 16; i += 128) sm.stage[i] = g_pw3m[cbase * 16 + i];
        if (b < cnt) sm.sb3[b] = g_pb3[cbase + b];
        __syncthreads();
        for (int j = 0; j < cnt; j++) {
            const float4* wq = (const float4*)&sm.stage[j * 16];
            float4 w0 = wq[0], w1v = wq[1], w2v = wq[2], w3v = wq[3];
            float d = out[0]  * w0.x  + out[1]  * w0.y  + out[2]  * w0.z  + out[3]  * w0.w
                    + out[4]  * w1v.x + out[5]  * w1v.y + out[6]  * w1v.z + out[7]  * w1v.w
                    + out[8]  * w2v.x + out[9]  * w2v.y + out[10] * w2v.z + out[11] * w2v.w
                    + out[12] * w3v.x + out[13] * w3v.y + out[14] * w3v.z + out[15] * w3v.w;
            xe_out[(cbase + j) * Bb + b] = xb + sm.sb3[j] + d;
        }
    }
}

// ---------------- final: segment sum + masked transpose + count re-zero -----
__global__ void __launch_bounds__(128) k_final(const float* __restrict__ xe,
                                               float* __restrict__ out) {
    int n = blockIdx.x, b = threadIdx.x;
    float s = 0.f;
    if (n >= 1800) {
        int rs = g_rsD[n], re = g_rsD[n + 1];
        for (int p = rs; p < re; p++) s += xe[g_rowidx[p] + b];
    }
    out[b * Nn + n] = s;
    if (b == 0) { g_cntD[n] = 0; g_cntS[n] = 0; }
}

// ---------------- launch ----------------------------------------------------
extern "C" void kernel_launch(void* const* d_in, const int* in_sizes, int n_in,
                              void* d_out, int out_size) {
    const float* x   = (const float*)d_in[0];
    const float* w1  = (const float*)d_in[1];
    const float* b1  = (const float*)d_in[2];
    const float* w2  = (const float*)d_in[3];
    const float* b2  = (const float*)d_in[4];
    const float* w3  = (const float*)d_in[5];
    const float* b3  = (const float*)d_in[6];
    const float* g1  = (const float*)d_in[7];
    const float* be1 = (const float*)d_in[8];
    const float* g2  = (const float*)d_in[9];
    const float* be2 = (const float*)d_in[10];
    const int*   ei  = (const int*)d_in[11];
    float* out = (float*)d_out;

    const int* src = ei;
    const int* dst = ei + Ee;

    k_init<<<(Nn * Bb + 255) / 256, 256>>>(x, src, dst);
    k_scan<<<2, 1024>>>();
    k_build<<<(Ee + 255) / 256, 256>>>(w1, w3, b3, src, dst);

    static float* xeA = nullptr;
    static float* xeB = nullptr;
    static float* xT  = nullptr;
    if (!xeA) {
        cudaGetSymbolAddress((void**)&xeA, g_xeA);
        cudaGetSymbolAddress((void**)&xeB, g_xeB);
        cudaGetSymbolAddress((void**)&xT,  g_xT);
    }

    k_layer<<<2000, 128>>>(xT,  1, xeA, b1, w2, b2, g1, be1, g2, be2);
    k_layer<<<1600, 128>>>(xeA, 0, xeB, b1, w2, b2, g1, be1, g2, be2);
    k_layer<<<1600, 128>>>(xeB, 0, xeA, b1, w2, b2, g1, be1, g2, be2);
    k_layer<<<1600, 128>>>(xeA, 0, xeB, b1, w2, b2, g1, be1, g2, be2);

    k_final<<<Nn, 128>>>(xeB, out);
}

// round 9
// speedup vs baseline: 1.6393x; 1.0192x over previous
#include <cuda_runtime.h>
#include <math.h>

#define Nn 2000
#define Ee 20000
#define Cc 16
#define Bb 128
#define EPS 1e-5f
#define CHUNK 128   // edges staged per smem chunk

typedef unsigned long long u64;

__device__ __forceinline__ bool is_func(int n) { return n >= 200 && n < 1800; }

// ---- packed f32x2 helpers ---------------------------------------------------
__device__ __forceinline__ u64 fma2(u64 a, u64 b, u64 c) {
    u64 d;
    asm("fma.rn.f32x2 %0, %1, %2, %3;" : "=l"(d) : "l"(a), "l"(b), "l"(c));
    return d;
}
__device__ __forceinline__ u64 splat2(float x) {
    u64 d;
    unsigned r = __float_as_uint(x);
    asm("mov.b64 %0, {%1, %1};" : "=l"(d) : "r"(r));
    return d;
}
__device__ __forceinline__ void unpack2(u64 v, float& lo, float& hi) {
    unsigned a, b;
    asm("mov.b64 {%0, %1}, %2;" : "=r"(a), "=r"(b) : "l"(v));
    lo = __uint_as_float(a); hi = __uint_as_float(b);
}
__device__ __forceinline__ u64 pack2(float lo, float hi) {
    u64 d;
    unsigned a = __float_as_uint(lo), b = __float_as_uint(hi);
    asm("mov.b64 %0, {%1, %2};" : "=l"(d) : "r"(a), "r"(b));
    return d;
}

// ---------------- device scratch (allocation-free) --------------------------
__device__ float g_xT[Nn * Bb];
__device__ float g_xeA[Ee * Bb];
__device__ float g_xeB[Ee * Bb];
__device__ float g_pw1[Ee * Cc];       // w1 in dst-CSR order
__device__ float g_pw3m[Ee * Cc];      // w3*fm[src] in src-CSR order
__device__ float g_pb3[Ee];            // b3 in src-CSR order
__device__ int   g_psrcd[Ee];          // src-node row offset (*Bb), dst order
__device__ int   g_rowidx[Ee];         // src-CSR row offset (*Bb), dst order
__device__ int   g_cntD[Nn], g_cntS[Nn];   // zero at load; re-zeroed by k_final
__device__ int   g_rsD[Nn + 1], g_rsS[Nn + 1];
__device__ int   g_curD[Nn], g_curS[Nn];

// ---------------- preprocessing ---------------------------------------------
__global__ void k_init(const float* __restrict__ x,
                       const int* __restrict__ src, const int* __restrict__ dst) {
    int t = blockIdx.x * blockDim.x + threadIdx.x;
    if (t < Ee) {
        atomicAdd(&g_cntD[dst[t]], 1);
        atomicAdd(&g_cntS[src[t]], 1);
    }
    if (t < Nn * Bb) {
        int n = t >> 7, b = t & 127;
        g_xT[t] = x[b * Nn + n];
    }
}

__global__ void __launch_bounds__(1024) k_scan() {
    __shared__ int sh[2048];
    const int* cnt = blockIdx.x ? g_cntS : g_cntD;
    int* rs  = blockIdx.x ? g_rsS : g_rsD;
    int* cur = blockIdx.x ? g_curS : g_curD;
    int t = threadIdx.x;
    sh[t]        = (t < Nn) ? cnt[t] : 0;
    sh[t + 1024] = (t + 1024 < Nn) ? cnt[t + 1024] : 0;
    __syncthreads();
    for (int off = 1; off < 2048; off <<= 1) {
        int v0 = (t >= off) ? sh[t - off] : 0;
        int v1 = (t + 1024 >= off) ? sh[t + 1024 - off] : 0;
        __syncthreads();
        sh[t] += v0;
        sh[t + 1024] += v1;
        __syncthreads();
    }
    if (t < Nn) {
        int v = (t == 0) ? 0 : sh[t - 1];
        rs[t] = v; cur[t] = v;
    }
    int i2 = t + 1024;
    if (i2 < Nn) {
        int v = sh[i2 - 1];
        rs[i2] = v; cur[i2] = v;
    }
    if (t == 0) rs[Nn] = sh[Nn - 1];
}

// CSR build: per-thread position compute, block-cooperative coalesced copy
__global__ void __launch_bounds__(256) k_build(
        const float* __restrict__ w1, const float* __restrict__ w3,
        const float* __restrict__ b3,
        const int* __restrict__ src, const int* __restrict__ dst) {
    __shared__ int sE[256], sPd[256], sPs[256];
    __shared__ float sFm[256];
    int e = blockIdx.x * 256 + threadIdx.x;
    int nEdge = min(256, Ee - blockIdx.x * 256);
    if (e < Ee) {
        int s = src[e], d = dst[e];
        int pd = atomicAdd(&g_curD[d], 1);
        int ps = atomicAdd(&g_curS[s], 1);
        g_psrcd[pd]  = s * Bb;
        g_rowidx[pd] = ps * Bb;
        g_pb3[ps]    = b3[e];
        sE[threadIdx.x]  = e;
        sPd[threadIdx.x] = pd;
        sPs[threadIdx.x] = ps;
        sFm[threadIdx.x] = is_func(s) ? 1.0f : 0.0f;
    }
    __syncthreads();
    // 16 consecutive threads copy one edge's 16-float row (coalesced 64B)
    for (int i = threadIdx.x; i < nEdge * 16; i += 256) {
        int j = i >> 4, c = i & 15;
        int e2 = sE[j];
        g_pw1[sPd[j] * 16 + c]  = w1[e2 * 16 + c];
        g_pw3m[sPs[j] * 16 + c] = w3[e2 * 16 + c] * sFm[j];
    }
}

// ---------------- shared layout (stage aliases shh; usage disjoint) ----------
struct SmemT {
    union {
        float4 stage4[CHUNK * 4];  // forces 16B alignment for ulonglong2 reads
        float  stage[CHUNK * 16];
        float  shh[128][17];
    };
    float4 shw4[16][4];
    float  shs[8][16], shs2[8][16];
    float  shscale[16], shshift[16];
    int    sidx[CHUNK];
    float  sb3[CHUNK];
};

// ---------------- BN + ELU (scalar) -----------------------------------------
__device__ __forceinline__ void bn_elu(float* acc, int n, int b,
                                       const float* __restrict__ gamma,
                                       const float* __restrict__ beta,
                                       SmemT* sm) {
    __syncthreads();
#pragma unroll
    for (int c = 0; c < 16; c++) sm->shh[b][c] = acc[c];
    __syncthreads();
    int c0 = b & 15, gg = b >> 4;
    float s = 0.f, s2 = 0.f;
#pragma unroll
    for (int k = 0; k < 16; k++) {
        float v = sm->shh[gg + 8 * k][c0];
        s += v; s2 += v * v;
    }
    sm->shs[gg][c0] = s;
    sm->shs2[gg][c0] = s2;
    __syncthreads();
    if (b < 16) {
        float S = 0.f, S2 = 0.f;
#pragma unroll
        for (int g = 0; g < 8; g++) { S += sm->shs[g][b]; S2 += sm->shs2[g][b]; }
        float m   = S * (1.0f / 128.0f);
        float var = S2 * (1.0f / 128.0f) - m * m;
        float rsg = rsqrtf(var + EPS);
        float sc  = gamma[n * 16 + b] * rsg;
        sm->shscale[b] = sc;
        sm->shshift[b] = beta[n * 16 + b] - m * sc;
    }
    __syncthreads();
#pragma unroll
    for (int c = 0; c < 16; c++) {
        float v = acc[c] * sm->shscale[c] + sm->shshift[c];
        acc[c] = v > 0.f ? v : (__expf(v) - 1.0f);
    }
}

// ---------------- fused per-layer kernel -------------------------------------
__global__ void __launch_bounds__(128, 11) k_layer(
    const float* __restrict__ xe_rows, int use_psrc,
    float* __restrict__ xe_out,
    const float* __restrict__ b1, const float* __restrict__ w2,
    const float* __restrict__ b2,
    const float* __restrict__ g1, const float* __restrict__ be1,
    const float* __restrict__ g2, const float* __restrict__ be2) {
    __shared__ SmemT sm;
    int t = blockIdx.x;
    int b = threadIdx.x;

    if (t >= 1600) {   // const-edge writer (layer-0 grid only)
        int i = t - 1600;
        int n = (i < 200) ? i : (1600 + i);
        float xb = g_xT[n * Bb + b];
        int qs = g_rsS[n], qe = g_rsS[n + 1];
        for (int q = qs; q < qe; q++) {
            float v = xb + g_pb3[q];
            g_xeA[q * Bb + b] = v;
            g_xeB[q * Bb + b] = v;
        }
        return;
    }

    int n = 200 + t;
    const int* rowix = use_psrc ? g_psrcd : g_rowidx;

    // acc as 8 packed f32x2 (channel pairs), init from b1
    u64 acc2[8];
    {
        const ulonglong2* bp = (const ulonglong2*)(b1 + n * 16);
#pragma unroll
        for (int k = 0; k < 4; k++) {
            ulonglong2 q = bp[k];
            acc2[2 * k] = q.x; acc2[2 * k + 1] = q.y;
        }
    }

    // ---- gather: staged weights, packed FMA ----
    int rs = g_rsD[n], re = g_rsD[n + 1];
    for (int cbase = rs; cbase < re; cbase += CHUNK) {
        int cnt = min(CHUNK, re - cbase);
        __syncthreads();
        for (int i = b; i < cnt * 16; i += 128) sm.stage[i] = g_pw1[cbase * 16 + i];
        if (b < cnt) sm.sidx[b] = rowix[cbase + b];
        __syncthreads();
        for (int jb = 0; jb < cnt; jb += 8) {
            float xv[8];
#pragma unroll
            for (int j = 0; j < 8; j++) {
                int jj = jb + j;
                xv[j] = (jj < cnt) ? xe_rows[sm.sidx[jj] + b] : 0.0f;
            }
#pragma unroll
            for (int j = 0; j < 8; j++) {
                int jj = jb + j;
                if (jj < cnt) {
                    u64 xv2 = splat2(xv[j]);
                    const ulonglong2* wp = (const ulonglong2*)&sm.stage[jj * 16];
                    ulonglong2 q0 = wp[0], q1 = wp[1], q2 = wp[2], q3 = wp[3];
                    acc2[0] = fma2(q0.x, xv2, acc2[0]);
                    acc2[1] = fma2(q0.y, xv2, acc2[1]);
                    acc2[2] = fma2(q1.x, xv2, acc2[2]);
                    acc2[3] = fma2(q1.y, xv2, acc2[3]);
                    acc2[4] = fma2(q2.x, xv2, acc2[4]);
                    acc2[5] = fma2(q2.y, xv2, acc2[5]);
                    acc2[6] = fma2(q3.x, xv2, acc2[6]);
                    acc2[7] = fma2(q3.y, xv2, acc2[7]);
                }
            }
        }
    }

    float acc[16];
#pragma unroll
    for (int k = 0; k < 8; k++) unpack2(acc2[k], acc[2 * k], acc[2 * k + 1]);

    bn_elu(acc, n, b, g1, be1, &sm);

    // ---- 16x16 matmul: park h in shh, packed FMA over output pairs ----
    __syncthreads();
#pragma unroll
    for (int c = 0; c < 16; c++) sm.shh[b][c] = acc[c];
    {
        const float4* w2p = (const float4*)(w2 + n * 256);
        for (int i = b; i < 64; i += 128) sm.shw4[i >> 2][i & 3] = w2p[i];
    }
    __syncthreads();

    u64 out2[8];
    {
        const ulonglong2* bp = (const ulonglong2*)(b2 + n * 16);
#pragma unroll
        for (int k = 0; k < 4; k++) {
            ulonglong2 q = bp[k];
            out2[2 * k] = q.x; out2[2 * k + 1] = q.y;
        }
    }
#pragma unroll
    for (int c = 0; c < 16; c++) {
        u64 v2 = splat2(sm.shh[b][c]);
        const ulonglong2* wp = (const ulonglong2*)&sm.shw4[c][0];
        ulonglong2 q0 = wp[0], q1 = wp[1], q2 = wp[2], q3 = wp[3];
        out2[0] = fma2(q0.x, v2, out2[0]);
        out2[1] = fma2(q0.y, v2, out2[1]);
        out2[2] = fma2(q1.x, v2, out2[2]);
        out2[3] = fma2(q1.y, v2, out2[3]);
        out2[4] = fma2(q2.x, v2, out2[4]);
        out2[5] = fma2(q2.y, v2, out2[5]);
        out2[6] = fma2(q3.x, v2, out2[6]);
        out2[7] = fma2(q3.y, v2, out2[7]);
    }

    float out[16];
#pragma unroll
    for (int k = 0; k < 8; k++) unpack2(out2[k], out[2 * k], out[2 * k + 1]);

    bn_elu(out, n, b, g2, be2, &sm);

#pragma unroll
    for (int k = 0; k < 8; k++) out2[k] = pack2(out[2 * k], out[2 * k + 1]);

    // ---- scatter: staged w3m + b3, packed dot ----
    float xb = g_xT[n * Bb + b];
    int qs = g_rsS[n], qe = g_rsS[n + 1];
    for (int cbase = qs; cbase < qe; cbase += CHUNK) {
        int cnt = min(CHUNK, qe - cbase);
        __syncthreads();
        for (int i = b; i < cnt * 16; i += 128) sm.stage[i] = g_pw3m[cbase * 16 + i];
        if (b < cnt) sm.sb3[b] = g_pb3[cbase + b];
        __syncthreads();
        for (int j = 0; j < cnt; j++) {
            const ulonglong2* wq = (const ulonglong2*)&sm.stage[j * 16];
            ulonglong2 q0 = wq[0], q1 = wq[1], q2 = wq[2], q3 = wq[3];
            u64 s2 = 0ULL;
            s2 = fma2(q0.x, out2[0], s2);
            s2 = fma2(q0.y, out2[1], s2);
            s2 = fma2(q1.x, out2[2], s2);
            s2 = fma2(q1.y, out2[3], s2);
            s2 = fma2(q2.x, out2[4], s2);
            s2 = fma2(q2.y, out2[5], s2);
            s2 = fma2(q3.x, out2[6], s2);
            s2 = fma2(q3.y, out2[7], s2);
            float lo, hi;
            unpack2(s2, lo, hi);
            xe_out[(cbase + j) * Bb + b] = xb + sm.sb3[j] + (lo + hi);
        }
    }
}

// ---------------- final: segment sum + masked transpose + count re-zero -----
__global__ void __launch_bounds__(128) k_final(const float* __restrict__ xe,
                                               float* __restrict__ out) {
    int n = blockIdx.x, b = threadIdx.x;
    float s = 0.f;
    if (n >= 1800) {
        int rs = g_rsD[n], re = g_rsD[n + 1];
        for (int p = rs; p < re; p++) s += xe[g_rowidx[p] + b];
    }
    out[b * Nn + n] = s;
    if (b == 0) { g_cntD[n] = 0; g_cntS[n] = 0; }
}

// ---------------- launch ----------------------------------------------------
extern "C" void kernel_launch(void* const* d_in, const int* in_sizes, int n_in,
                              void* d_out, int out_size) {
    const float* x   = (const float*)d_in[0];
    const float* w1  = (const float*)d_in[1];
    const float* b1  = (const float*)d_in[2];
    const float* w2  = (const float*)d_in[3];
    const float* b2  = (const float*)d_in[4];
    const float* w3  = (const float*)d_in[5];
    const float* b3  = (const float*)d_in[6];
    const float* g1  = (const float*)d_in[7];
    const float* be1 = (const float*)d_in[8];
    const float* g2  = (const float*)d_in[9];
    const float* be2 = (const float*)d_in[10];
    const int*   ei  = (const int*)d_in[11];
    float* out = (float*)d_out;

    const int* src = ei;
    const int* dst = ei + Ee;

    k_init<<<(Nn * Bb + 255) / 256, 256>>>(x, src, dst);
    k_scan<<<2, 1024>>>();
    k_build<<<(Ee + 255) / 256, 256>>>(w1, w3, b3, src, dst);

    static float* xeA = nullptr;
    static float* xeB = nullptr;
    static float* xT  = nullptr;
    if (!xeA) {
        cudaGetSymbolAddress((void**)&xeA, g_xeA);
        cudaGetSymbolAddress((void**)&xeB, g_xeB);
        cudaGetSymbolAddress((void**)&xT,  g_xT);
    }

    k_layer<<<2000, 128>>>(xT,  1, xeA, b1, w2, b2, g1, be1, g2, be2);
    k_layer<<<1600, 128>>>(xeA, 0, xeB, b1, w2, b2, g1, be1, g2, be2);
    k_layer<<<1600, 128>>>(xeB, 0, xeA, b1, w2, b2, g1, be1, g2, be2);
    k_layer<<<1600, 128>>>(xeA, 0, xeB, b1, w2, b2, g1, be1, g2, be2);

    k_final<<<Nn, 128>>>(xeB, out);
}